// round 1
// baseline (speedup 1.0000x reference)
#include <cuda_runtime.h>
#include <math.h>

#define EMBED 2048
#define NEXP  64
#define TOPK  8
#define TT    64          // tokens per CTA
#define KC    64          // K chunk
#define RS    (KC + 4)    // smem row stride (floats), 16B-aligned, conflict-softened
#define TPB   256
#define MAXBLK 1024

// Deterministic aux-loss accumulators (no device-side allocation allowed).
__device__ float        g_pi_part[MAXBLK][NEXP];
__device__ unsigned int g_cnt[NEXP];

__global__ void zero_cnt_kernel() {
    if (threadIdx.x < NEXP) g_cnt[threadIdx.x] = 0u;
}

__global__ __launch_bounds__(TPB) void gate_kernel(
    const float* __restrict__ x, const float* __restrict__ w,
    float* __restrict__ out, int ntok)
{
    __shared__ float smem[2 * TT * RS];      // X tile + W tile; aliased as logits later
    __shared__ float piS[NEXP];
    __shared__ unsigned int cntS[NEXP];

    float (*Xs)[RS] = (float (*)[RS])smem;
    float (*Ws)[RS] = (float (*)[RS])(smem + TT * RS);

    const int tid = threadIdx.x;
    const int tx = tid & 15, ty = tid >> 4;
    const int t0 = ty * 4, e0 = tx * 4;
    const long tok_base = (long)blockIdx.x * TT;

    if (tid < NEXP) { piS[tid] = 0.f; cntS[tid] = 0u; }

    float acc[4][4];
    #pragma unroll
    for (int i = 0; i < 4; i++)
        #pragma unroll
        for (int j = 0; j < 4; j++)
            acc[i][j] = 0.f;

    // ---------------- GEMM: logits[64 tok][64 exp] ----------------
    for (int kc = 0; kc < EMBED; kc += KC) {
        __syncthreads();   // also covers piS/cntS init on first pass
        #pragma unroll
        for (int r = 0; r < 4; r++) {
            int idx = tid + r * TPB;        // 0..1023
            int t = idx >> 4;               // 0..63 (token for X, expert for W)
            int c = (idx & 15) << 2;        // 0..60 step 4
            float4 xv4 = *(const float4*)(x + (tok_base + t) * EMBED + kc + c);
            *(float4*)&Xs[t][c] = xv4;
            float4 wv4 = *(const float4*)(w + (long)t * EMBED + kc + c);
            *(float4*)&Ws[t][c] = wv4;
        }
        __syncthreads();

        #pragma unroll
        for (int k = 0; k < KC; k += 4) {
            float4 xv[4], wv[4];
            #pragma unroll
            for (int i = 0; i < 4; i++) xv[i] = *(float4*)&Xs[t0 + i][k];
            #pragma unroll
            for (int j = 0; j < 4; j++) wv[j] = *(float4*)&Ws[e0 + j][k];
            #pragma unroll
            for (int i = 0; i < 4; i++)
                #pragma unroll
                for (int j = 0; j < 4; j++) {
                    acc[i][j] = fmaf(xv[i].x, wv[j].x, acc[i][j]);
                    acc[i][j] = fmaf(xv[i].y, wv[j].y, acc[i][j]);
                    acc[i][j] = fmaf(xv[i].z, wv[j].z, acc[i][j]);
                    acc[i][j] = fmaf(xv[i].w, wv[j].w, acc[i][j]);
                }
        }
    }

    // ---------------- logits -> smem (aliased over X/W tiles) ----------------
    __syncthreads();
    float (*L)[NEXP + 1] = (float (*)[NEXP + 1])smem;
    #pragma unroll
    for (int i = 0; i < 4; i++)
        #pragma unroll
        for (int j = 0; j < 4; j++)
            L[t0 + i][e0 + j] = acc[i][j];
    __syncthreads();

    // ---------------- softmax + top-8 (one warp per 8 tokens) ----------------
    const int lane = tid & 31, wid = tid >> 5;
    float pi0 = 0.f, pi1 = 0.f;

    for (int r = 0; r < 8; r++) {
        int t = wid * 8 + r;
        float s0 = L[t][lane], s1 = L[t][lane + 32];
        float m = fmaxf(s0, s1);
        #pragma unroll
        for (int off = 16; off; off >>= 1)
            m = fmaxf(m, __shfl_xor_sync(0xffffffffu, m, off));
        float e0v = expf(s0 - m), e1v = expf(s1 - m);
        float ssum = e0v + e1v;
        #pragma unroll
        for (int off = 16; off; off >>= 1)
            ssum += __shfl_xor_sync(0xffffffffu, ssum, off);
        float p0 = e0v / ssum, p1 = e1v / ssum;
        pi0 += p0; pi1 += p1;

        float v0 = p0, v1 = p1;
        long gt = tok_base + t;
        #pragma unroll
        for (int kk = 0; kk < TOPK; kk++) {
            float v; int idx;
            if (v1 > v0) { v = v1; idx = lane + 32; }   // strict >: ties prefer lower idx
            else         { v = v0; idx = lane; }
            #pragma unroll
            for (int off = 16; off; off >>= 1) {
                float ov = __shfl_xor_sync(0xffffffffu, v, off);
                int   oi = __shfl_xor_sync(0xffffffffu, idx, off);
                if (ov > v || (ov == v && oi < idx)) { v = ov; idx = oi; }
            }
            if (lane == 0) {
                out[gt * TOPK + kk] = (float)idx;
                out[(long)ntok * TOPK + gt * TOPK + kk] = v;
                atomicAdd(&cntS[idx], 1u);
            }
            if (idx == lane)      v0 = -1.f;
            if (idx == lane + 32) v1 = -1.f;
        }
    }

    atomicAdd(&piS[lane], pi0);
    atomicAdd(&piS[lane + 32], pi1);
    __syncthreads();
    if (tid < NEXP) {
        g_pi_part[blockIdx.x][tid] = piS[tid];                 // deterministic partials
        if (cntS[tid]) atomicAdd(&g_cnt[tid], cntS[tid]);      // integer atomics: deterministic
    }
}

__global__ void finalize_kernel(float* __restrict__ aux, int nblocks, float ntokf) {
    int e = threadIdx.x;   // 64 threads
    float s = 0.f;
    for (int b = 0; b < nblocks; b++) s += g_pi_part[b][e];
    float Pi = s / ntokf;
    float ce = (float)g_cnt[e] / (ntokf * (float)TOPK);
    float v = Pi * ce * (float)NEXP;
    __shared__ float red[2];
    #pragma unroll
    for (int off = 16; off; off >>= 1)
        v += __shfl_xor_sync(0xffffffffu, v, off);
    if ((e & 31) == 0) red[e >> 5] = v;
    __syncthreads();
    if (e == 0) aux[0] = (red[0] + red[1]) * 0.01f;
}

extern "C" void kernel_launch(void* const* d_in, const int* in_sizes, int n_in,
                              void* d_out, int out_size) {
    const float* x = (const float*)d_in[0];
    const float* w = (const float*)d_in[1];
    float* out = (float*)d_out;
    int ntok = in_sizes[0] / EMBED;       // 32768
    int nblocks = ntok / TT;              // 512
    zero_cnt_kernel<<<1, 64>>>();
    gate_kernel<<<nblocks, TPB>>>(x, w, out, ntok);
    finalize_kernel<<<1, 64>>>(out + (long)ntok * 2 * TOPK, nblocks, (float)ntok);
}

// round 4
// speedup vs baseline: 2.0122x; 2.0122x over previous
#include <cuda_runtime.h>
#include <math.h>

#define EMBED   2048
#define NEXP    64
#define TOPK    8
#define KC      16                 // K-chunk
#define NCHUNK  (EMBED / KC)       // 128
#define TPT     2                  // tokens per thread
#define TOKS    64                 // tokens per CTA (32 threads x 2)
#define NBLK    512

typedef unsigned long long u64;

__device__ float        g_wt[EMBED * NEXP];   // W transposed: [k][e]
__device__ float        g_pi_part[NBLK][NEXP];
__device__ unsigned int g_cnt[NEXP];

// One-shot per launch: transpose W into g_wt, zero counters.
__global__ void prep_kernel(const float* __restrict__ w) {
    int idx = blockIdx.x * blockDim.x + threadIdx.x;   // e*2048 + k
    int e = idx >> 11, k = idx & 2047;
    g_wt[k * NEXP + e] = w[idx];
    if (idx < NEXP) g_cnt[idx] = 0u;
}

__device__ __forceinline__ u64 ffma2(u64 a, u64 b, u64 c) {
    u64 d;
    asm("fma.rn.f32x2 %0, %1, %2, %3;" : "=l"(d) : "l"(a), "l"(b), "l"(c));
    return d;
}
__device__ __forceinline__ u64 pack2(float f) {
    u64 d;
    asm("mov.b64 %0, {%1, %1};" : "=l"(d) : "f"(f));
    return d;
}
__device__ __forceinline__ void lds_v2(u64& a, u64& b, unsigned addr) {
    asm volatile("ld.shared.v2.b64 {%0, %1}, [%2];" : "=l"(a), "=l"(b) : "r"(addr));
}
__device__ __forceinline__ void cp_async16(unsigned saddr, const void* gaddr) {
    asm volatile("cp.async.ca.shared.global [%0], [%1], 16;" :: "r"(saddr), "l"(gaddr));
}
__device__ __forceinline__ void cp_commit() { asm volatile("cp.async.commit_group;"); }
__device__ __forceinline__ void cp_wait1()  { asm volatile("cp.async.wait_group 1;" ::: "memory"); }
__device__ __forceinline__ void cp_wait0()  { asm volatile("cp.async.wait_group 0;" ::: "memory"); }

__device__ __forceinline__ void load16(float (&d)[16], const float* p) {
    #pragma unroll
    for (int i = 0; i < 4; i++) {
        float4 v = *(const float4*)(p + i * 4);
        d[i * 4 + 0] = v.x; d[i * 4 + 1] = v.y; d[i * 4 + 2] = v.z; d[i * 4 + 3] = v.w;
    }
}

// Softmax with round-1-faithful numerics: sequential-k logits already in `a`
// (lane0 = even expert, lane1 = odd), expf, butterfly sum (offsets 16..1), IEEE div.
__device__ __forceinline__ void softmax_row(const u64 (&a)[32], float (&p)[NEXP]) {
    float l[NEXP];
    #pragma unroll
    for (int m = 0; m < 32; m++) {
        unsigned lo, hi;
        asm("mov.b64 {%0, %1}, %2;" : "=r"(lo), "=r"(hi) : "l"(a[m]));
        l[2 * m]     = __uint_as_float(lo);
        l[2 * m + 1] = __uint_as_float(hi);
    }
    float mx = l[0];
    #pragma unroll
    for (int e = 1; e < NEXP; e++) mx = fmaxf(mx, l[e]);
    float ex[NEXP];
    #pragma unroll
    for (int e = 0; e < NEXP; e++) ex[e] = expf(l[e] - mx);
    float v[32];
    #pragma unroll
    for (int j = 0; j < 32; j++) v[j] = ex[j] + ex[j + 32];
    #pragma unroll
    for (int off = 16; off >= 1; off >>= 1) {
        float nv[32];
        #pragma unroll
        for (int j = 0; j < 32; j++) nv[j] = v[j] + v[j ^ off];
        #pragma unroll
        for (int j = 0; j < 32; j++) v[j] = nv[j];
    }
    float s = v[0];
    #pragma unroll
    for (int e = 0; e < NEXP; e++) p[e] = ex[e] / s;
}

__global__ void __launch_bounds__(32) gate_kernel(
    const float* __restrict__ x, float* __restrict__ out, int ntok)
{
    __shared__ __align__(16) float wbuf[2][KC * NEXP];   // 2 x 4KB Wt double buffer
    __shared__ float Ls[TOKS][NEXP + 1];
    __shared__ unsigned int cntS[NEXP];

    const int t = threadIdx.x;
    const long tok0 = (long)blockIdx.x * TOKS + 2 * t;
    const float* xr0 = x + tok0 * EMBED;
    const float* xr1 = xr0 + EMBED;
    cntS[t] = 0u; cntS[t + 32] = 0u;

    u64 acc0[32], acc1[32];
    #pragma unroll
    for (int m = 0; m < 32; m++) { acc0[m] = 0ULL; acc1[m] = 0ULL; }

    const unsigned wb[2] = {
        (unsigned)__cvta_generic_to_shared(&wbuf[0][0]),
        (unsigned)__cvta_generic_to_shared(&wbuf[1][0])
    };

    // stage Wt chunk 0 (contiguous 4KB)
    #pragma unroll
    for (int j = 0; j < 8; j++) {
        int f = t + j * 32;
        cp_async16(wb[0] + f * 16, g_wt + f * 4);
    }
    cp_commit();

    float xa0[16], xa1[16], xn0[16], xn1[16];
    load16(xa0, xr0); load16(xa1, xr1);

    for (int c = 0; c < NCHUNK; c++) {
        if (c + 1 < NCHUNK) {
            unsigned dst = wb[(c + 1) & 1];
            const float* src = g_wt + (c + 1) * (KC * NEXP);
            #pragma unroll
            for (int j = 0; j < 8; j++) {
                int f = t + j * 32;
                cp_async16(dst + f * 16, src + f * 4);
            }
            cp_commit();
            load16(xn0, xr0 + (c + 1) * KC);
            load16(xn1, xr1 + (c + 1) * KC);
            cp_wait1();
        } else {
            cp_wait0();
        }
        __syncwarp();

        const unsigned base = wb[c & 1];
        #pragma unroll
        for (int k = 0; k < KC; k++) {
            u64 a0 = pack2(xa0[k]);
            u64 a1 = pack2(xa1[k]);
            #pragma unroll
            for (int m = 0; m < 16; m++) {
                u64 b0, b1;
                lds_v2(b0, b1, base + k * (NEXP * 4) + m * 16);
                acc0[2 * m]     = ffma2(a0, b0, acc0[2 * m]);
                acc0[2 * m + 1] = ffma2(a0, b1, acc0[2 * m + 1]);
                acc1[2 * m]     = ffma2(a1, b0, acc1[2 * m]);
                acc1[2 * m + 1] = ffma2(a1, b1, acc1[2 * m + 1]);
            }
        }
        if (c + 1 < NCHUNK) {
            #pragma unroll
            for (int i = 0; i < 16; i++) { xa0[i] = xn0[i]; xa1[i] = xn1[i]; }
        }
    }

    // ---------------- epilogue ----------------
    {
        float p[NEXP];
        softmax_row(acc0, p);
        #pragma unroll
        for (int e = 0; e < NEXP; e++) Ls[2 * t][e] = p[e];
        softmax_row(acc1, p);
        #pragma unroll
        for (int e = 0; e < NEXP; e++) Ls[2 * t + 1][e] = p[e];
    }
    __syncthreads();

    // per-CTA Pi partials (deterministic fixed order)
    {
        float s1 = 0.f, s2 = 0.f;
        #pragma unroll
        for (int r = 0; r < TOKS; r++) { s1 += Ls[r][t]; s2 += Ls[r][t + 32]; }
        g_pi_part[blockIdx.x][t] = s1;
        g_pi_part[blockIdx.x][t + 32] = s2;
    }
    __syncthreads();   // Pi reads done before top-k mutates Ls

    // top-8 per token: ascending scan, strict > => lowest index wins ties
    #pragma unroll
    for (int tt = 0; tt < TPT; tt++) {
        const int row = 2 * t + tt;
        const long tok = tok0 + tt;
        #pragma unroll 1
        for (int kk = 0; kk < TOPK; kk++) {
            float best = -1.f; int bi = 0;
            #pragma unroll
            for (int e = 0; e < NEXP; e++) {
                float v = Ls[row][e];
                if (v > best) { best = v; bi = e; }
            }
            Ls[row][bi] = -1.f;
            out[tok * TOPK + kk] = (float)bi;
            out[(long)ntok * TOPK + tok * TOPK + kk] = best;
            atomicAdd(&cntS[bi], 1u);
        }
    }
    __syncthreads();
    if (cntS[t])      atomicAdd(&g_cnt[t], cntS[t]);
    if (cntS[t + 32]) atomicAdd(&g_cnt[t + 32], cntS[t + 32]);
}

__global__ void finalize_kernel(float* __restrict__ aux, int nblocks, float ntokf) {
    int e = threadIdx.x;   // 64 threads
    float s = 0.f;
    for (int b = 0; b < nblocks; b++) s += g_pi_part[b][e];
    float Pi = s / ntokf;
    float ce = (float)g_cnt[e] / (ntokf * (float)TOPK);
    float v = Pi * ce * (float)NEXP;
    __shared__ float red[2];
    #pragma unroll
    for (int off = 16; off; off >>= 1)
        v += __shfl_xor_sync(0xffffffffu, v, off);
    if ((e & 31) == 0) red[e >> 5] = v;
    __syncthreads();
    if (e == 0) aux[0] = (red[0] + red[1]) * 0.01f;
}

extern "C" void kernel_launch(void* const* d_in, const int* in_sizes, int n_in,
                              void* d_out, int out_size) {
    const float* x = (const float*)d_in[0];
    const float* w = (const float*)d_in[1];
    float* out = (float*)d_out;
    int ntok = in_sizes[0] / EMBED;        // 32768
    int nblocks = ntok / TOKS;             // 512
    prep_kernel<<<(NEXP * EMBED) / 256, 256>>>(w);
    gate_kernel<<<nblocks, 32>>>(x, out, ntok);
    finalize_kernel<<<1, 64>>>(out + (long)ntok * 2 * TOPK, nblocks, (float)ntok);
}